// round 4
// baseline (speedup 1.0000x reference)
#include <cuda_runtime.h>
#include <math.h>

#define BB   8
#define NN   2048
#define KDIN 300
#define DD   96
#define MTOT (BB*NN)   // 16384

// ---------------- scratch (no runtime allocation allowed) ----------------
__device__ __align__(128) float g_h [3][MTOT][DD];
__device__ __align__(128) float g_a [3][MTOT][DD];
__device__ __align__(128) float g_z [3][MTOT][DD];
__device__ __align__(128) float g_rh[3][MTOT][DD];
__device__ __align__(128) float g_hp[3][MTOT][DD];
__device__ __align__(128) float g_t [3][MTOT][DD];

// ---------------- f32x2 helpers ----------------
__device__ __forceinline__ unsigned long long pack2(float x, float y) {
    unsigned long long r;
    asm("mov.b64 %0, {%1,%2};" : "=l"(r) : "f"(x), "f"(y));
    return r;
}
__device__ __forceinline__ float2 unpack2(unsigned long long v) {
    float2 f;
    asm("mov.b64 {%0,%1}, %2;" : "=f"(f.x), "=f"(f.y) : "l"(v));
    return f;
}
__device__ __forceinline__ void ffma2(unsigned long long& acc, unsigned long long a, unsigned long long b) {
    asm("fma.rn.f32x2 %0, %1, %2, %0;" : "+l"(acc) : "l"(a), "l"(b));
}
__device__ __forceinline__ float sigmoidf_(float x) { return 1.f / (1.f + expf(-x)); }
__device__ __forceinline__ float lrelu(float v)     { return v > 0.f ? v : 0.2f * v; }

// ---------------- shared compute step: 64x96 tile, 32-deep K chunk -------
// thread layout: 256 = 16(tx: col groups of 6) x 16(ty: row groups of 4)
__device__ __forceinline__ void step32_64(const float Xs[64][32], const float Ws[32][96],
                                          int tx, int ty, unsigned long long acc[4][3])
{
    #pragma unroll
    for (int k = 0; k < 32; k++) {
        unsigned long long bp[3];
        #pragma unroll
        for (int q = 0; q < 3; q++)
            bp[q] = *(const unsigned long long*)&Ws[k][tx*6 + 2*q];
        #pragma unroll
        for (int i = 0; i < 4; i++) {
            float a = Xs[ty*4 + i][k];
            unsigned long long ap = pack2(a, a);
            #pragma unroll
            for (int q = 0; q < 3; q++) ffma2(acc[i][q], ap, bp[q]);
        }
    }
}

// ---------------- generic K=96 GEMM piece: acc += In[m0:m0+64, :] @ W[96,96]
__device__ __forceinline__ void mm96(const float* __restrict__ In, const float* __restrict__ W,
                                     int m0, int tid, unsigned long long acc[4][3])
{
    __shared__ __align__(16) float Xs[64][32];
    __shared__ __align__(16) float Ws[32][96];
    int tx = tid & 15, ty = tid >> 4;
    #pragma unroll 1
    for (int k0 = 0; k0 < DD; k0 += 32) {
        #pragma unroll
        for (int l = 0; l < 2; l++) {
            int e = tid + l*256;          // float4 index 0..511
            int r = e >> 3, k4 = e & 7;
            *(float4*)&Xs[r][k4*4] = *(const float4*)(In + (size_t)(m0 + r)*DD + k0 + k4*4);
        }
        #pragma unroll
        for (int l = 0; l < 3; l++) {
            int e = tid + l*256;          // float4 index 0..767
            int kk = e / 24, d4 = e % 24;
            *(float4*)&Ws[kk][d4*4] = *(const float4*)(W + (size_t)(k0 + kk)*DD + d4*4);
        }
        __syncthreads();
        step32_64(Xs, Ws, tx, ty, acc);
        __syncthreads();
    }
}

// variant for attention fusion: input tile = lrelu(T0 + T1)
__device__ __forceinline__ void mm96pairL(const float* __restrict__ T0, const float* __restrict__ T1,
                                          const float* __restrict__ W, int m0, int tid,
                                          unsigned long long acc[4][3])
{
    __shared__ __align__(16) float Xs[64][32];
    __shared__ __align__(16) float Ws[32][96];
    int tx = tid & 15, ty = tid >> 4;
    #pragma unroll 1
    for (int k0 = 0; k0 < DD; k0 += 32) {
        #pragma unroll
        for (int l = 0; l < 2; l++) {
            int e = tid + l*256;
            int r = e >> 3, k4 = e & 7;
            size_t off = (size_t)(m0 + r)*DD + k0 + k4*4;
            float4 u = *(const float4*)(T0 + off);
            float4 v = *(const float4*)(T1 + off);
            float4 w;
            w.x = lrelu(u.x + v.x); w.y = lrelu(u.y + v.y);
            w.z = lrelu(u.z + v.z); w.w = lrelu(u.w + v.w);
            *(float4*)&Xs[r][k4*4] = w;
        }
        #pragma unroll
        for (int l = 0; l < 3; l++) {
            int e = tid + l*256;
            int kk = e / 24, d4 = e % 24;
            *(float4*)&Ws[kk][d4*4] = *(const float4*)(W + (size_t)(k0 + kk)*DD + d4*4);
        }
        __syncthreads();
        step32_64(Xs, Ws, tx, ty, acc);
        __syncthreads();
    }
}

// ---------------- encode: h_i = mask_i * relu(x @ W_enc[i] + b_enc[i]) ----
__global__ __launch_bounds__(256) void encode_kernel(
    const float* __restrict__ x, const float* __restrict__ Wenc, const float* __restrict__ benc,
    const float* __restrict__ mk0, const float* __restrict__ mk1, const float* __restrict__ mk2)
{
    __shared__ __align__(16) float Xs[64][32];
    __shared__ __align__(16) float Ws[32][96];
    int br = blockIdx.y;
    int m0 = blockIdx.x * 64;
    const float* mask = (br == 0) ? mk0 : ((br == 1) ? mk1 : mk2);
    const float* W = Wenc + (size_t)br * KDIN * DD;
    int tid = threadIdx.x, tx = tid & 15, ty = tid >> 4;
    unsigned long long acc[4][3] = {};
    #pragma unroll 1
    for (int k0 = 0; k0 < 320; k0 += 32) {       // K=300 padded with guards
        #pragma unroll
        for (int l = 0; l < 8; l++) {
            int e = tid + l*256;                  // 0..2047
            int r = e >> 5, k = e & 31;
            int kk = k0 + k;
            Xs[r][k] = (kk < KDIN) ? x[(size_t)(m0 + r)*KDIN + kk] : 0.f;
        }
        #pragma unroll
        for (int l = 0; l < 12; l++) {
            int e = tid + l*256;                  // 0..3071
            int kk = e / 96, d = e % 96;
            int kg = k0 + kk;
            Ws[kk][d] = (kg < KDIN) ? W[(size_t)kg*DD + d] : 0.f;
        }
        __syncthreads();
        step32_64(Xs, Ws, tx, ty, acc);
        __syncthreads();
    }
    #pragma unroll
    for (int i = 0; i < 4; i++) {
        int m = m0 + ty*4 + i;
        float mkv = mask[m];
        #pragma unroll
        for (int q = 0; q < 3; q++) {
            float2 v = unpack2(acc[i][q]);
            int c = tx*6 + 2*q;
            float o0 = fmaxf(v.x + benc[br*DD + c],     0.f) * mkv;
            float o1 = fmaxf(v.y + benc[br*DD + c + 1], 0.f) * mkv;
            *(float2*)&g_h[br][m][c] = make_float2(o0, o1);
        }
    }
}

// ---------------- message passing: a = adj @ h (the hot GEMM) -------------
__global__ __launch_bounds__(256, 2) void msg_kernel(
    const float* __restrict__ adjA, const float* __restrict__ adjB, const float* __restrict__ adjC)
{
    __shared__ __align__(16) float As[128][32];
    __shared__ __align__(16) float Hs[32][96];
    int br = blockIdx.z, b = blockIdx.y;
    int n0 = blockIdx.x * 128;
    const float* adj = ((br == 0) ? adjA : ((br == 1) ? adjB : adjC)) + (size_t)b * NN * NN;
    const float* H = &g_h[br][b * NN][0];
    float* Ao = &g_a[br][b * NN][0];
    int tid = threadIdx.x, tx = tid & 15, ty = tid >> 4;
    unsigned long long acc[8][3] = {};
    #pragma unroll 1
    for (int k0 = 0; k0 < NN; k0 += 32) {
        #pragma unroll
        for (int l = 0; l < 4; l++) {
            int e = tid + l*256;                  // float4 index 0..1023
            int r = e >> 3, k4 = e & 7;
            *(float4*)&As[r][k4*4] = *(const float4*)(adj + (size_t)(n0 + r)*NN + k0 + k4*4);
        }
        #pragma unroll
        for (int l = 0; l < 3; l++) {
            int e = tid + l*256;                  // 0..767
            int kk = e / 24, d4 = e % 24;
            *(float4*)&Hs[kk][d4*4] = *(const float4*)(H + (size_t)(k0 + kk)*DD + d4*4);
        }
        __syncthreads();
        #pragma unroll
        for (int k = 0; k < 32; k++) {
            unsigned long long bp[3];
            #pragma unroll
            for (int q = 0; q < 3; q++)
                bp[q] = *(const unsigned long long*)&Hs[k][tx*6 + 2*q];
            #pragma unroll
            for (int i = 0; i < 8; i++) {
                float a = As[ty*8 + i][k];
                unsigned long long ap = pack2(a, a);
                #pragma unroll
                for (int q = 0; q < 3; q++) ffma2(acc[i][q], ap, bp[q]);
            }
        }
        __syncthreads();
    }
    #pragma unroll
    for (int i = 0; i < 8; i++) {
        int n = n0 + ty*8 + i;
        #pragma unroll
        for (int q = 0; q < 3; q++) {
            float2 v = unpack2(acc[i][q]);
            *(float2*)&Ao[(size_t)n*DD + tx*6 + 2*q] = v;
        }
    }
}

// ---------------- gates pass 1: z, r*h, a@Wh0+bh0 -------------------------
__global__ __launch_bounds__(256) void gates1_kernel(
    const float* __restrict__ Wgru, const float* __restrict__ bgru)
{
    int br = blockIdx.z, g = blockIdx.y;   // g: 0=z, 1=r, 2=h-part
    int m0 = blockIdx.x * 64;
    int tid = threadIdx.x, tx = tid & 15, ty = tid >> 4;
    unsigned long long acc[4][3] = {};
    int j0 = g * 2;                        // z:(0,1) r:(2,3) h:(4)
    mm96(&g_a[br][0][0], Wgru + (size_t)(br*6 + j0)*DD*DD, m0, tid, acc);
    if (g < 2)
        mm96(&g_h[br][0][0], Wgru + (size_t)(br*6 + j0 + 1)*DD*DD, m0, tid, acc);

    #pragma unroll
    for (int i = 0; i < 4; i++) {
        int m = m0 + ty*4 + i;
        #pragma unroll
        for (int q = 0; q < 3; q++) {
            float2 v = unpack2(acc[i][q]);
            int c = tx*6 + 2*q;
            if (g == 0) {
                float z0 = sigmoidf_(v.x + bgru[(br*6+0)*DD + c]     + bgru[(br*6+1)*DD + c]);
                float z1 = sigmoidf_(v.y + bgru[(br*6+0)*DD + c + 1] + bgru[(br*6+1)*DD + c + 1]);
                *(float2*)&g_z[br][m][c] = make_float2(z0, z1);
            } else if (g == 1) {
                float2 hv = *(const float2*)&g_h[br][m][c];
                float r0 = sigmoidf_(v.x + bgru[(br*6+2)*DD + c]     + bgru[(br*6+3)*DD + c]);
                float r1 = sigmoidf_(v.y + bgru[(br*6+2)*DD + c + 1] + bgru[(br*6+3)*DD + c + 1]);
                *(float2*)&g_rh[br][m][c] = make_float2(r0*hv.x, r1*hv.y);
            } else {
                *(float2*)&g_hp[br][m][c] = make_float2(v.x + bgru[(br*6+4)*DD + c],
                                                        v.y + bgru[(br*6+4)*DD + c + 1]);
            }
        }
    }
}

// ---------------- gates pass 2: hh & GRU blend, writes h in place ---------
__global__ __launch_bounds__(256) void gates2_kernel(
    const float* __restrict__ Wgru, const float* __restrict__ bgru,
    const float* __restrict__ mk0, const float* __restrict__ mk1, const float* __restrict__ mk2)
{
    int br = blockIdx.y;
    int m0 = blockIdx.x * 64;
    const float* mask = (br == 0) ? mk0 : ((br == 1) ? mk1 : mk2);
    int tid = threadIdx.x, tx = tid & 15, ty = tid >> 4;
    unsigned long long acc[4][3] = {};
    mm96(&g_rh[br][0][0], Wgru + (size_t)(br*6 + 5)*DD*DD, m0, tid, acc);

    #pragma unroll
    for (int i = 0; i < 4; i++) {
        int m = m0 + ty*4 + i;
        float mkv = mask[m];
        #pragma unroll
        for (int q = 0; q < 3; q++) {
            float2 v = unpack2(acc[i][q]);
            int c = tx*6 + 2*q;
            float2 hp = *(const float2*)&g_hp[br][m][c];
            float2 zv = *(const float2*)&g_z[br][m][c];
            float2 hv = *(const float2*)&g_h[br][m][c];
            float hh0 = fmaxf(mkv * (v.x + hp.x + bgru[(br*6+5)*DD + c]),     0.f);
            float hh1 = fmaxf(mkv * (v.y + hp.y + bgru[(br*6+5)*DD + c + 1]), 0.f);
            float o0 = hh0*zv.x + hv.x*(1.f - zv.x);
            float o1 = hh1*zv.y + hv.y*(1.f - zv.y);
            *(float2*)&g_h[br][m][c] = make_float2(o0, o1);
        }
    }
}

// ---------------- inter-propagation: t_i = s_i @ W_ii[i] + b_ii[i] --------
__global__ __launch_bounds__(256) void f1_kernel(
    const float* __restrict__ Wii, const float* __restrict__ bii)
{
    int br = blockIdx.y;
    int m0 = blockIdx.x * 64;
    int tid = threadIdx.x, tx = tid & 15, ty = tid >> 4;
    unsigned long long acc[4][3] = {};
    mm96(&g_h[br][0][0], Wii + (size_t)br*DD*DD, m0, tid, acc);
    #pragma unroll
    for (int i = 0; i < 4; i++) {
        int m = m0 + ty*4 + i;
        #pragma unroll
        for (int q = 0; q < 3; q++) {
            float2 v = unpack2(acc[i][q]);
            int c = tx*6 + 2*q;
            *(float2*)&g_t[br][m][c] = make_float2(v.x + bii[br*DD + c],
                                                   v.y + bii[br*DD + c + 1]);
        }
    }
}

// ---------------- attention fusion: out = sum_j lrelu(t_j+t_{j+1})@W_att[j]+b
__global__ __launch_bounds__(256) void f2_kernel(
    const float* __restrict__ Watt, const float* __restrict__ batt, float* __restrict__ out)
{
    int m0 = blockIdx.x * 64;
    int tid = threadIdx.x, tx = tid & 15, ty = tid >> 4;
    unsigned long long acc[4][3] = {};
    #pragma unroll 1
    for (int j = 0; j < 3; j++) {
        const float* T0 = &g_t[j][0][0];
        const float* T1 = &g_t[(j + 1) % 3][0][0];
        mm96pairL(T0, T1, Watt + (size_t)j*DD*DD, m0, tid, acc);
    }
    #pragma unroll
    for (int i = 0; i < 4; i++) {
        int m = m0 + ty*4 + i;
        #pragma unroll
        for (int q = 0; q < 3; q++) {
            float2 v = unpack2(acc[i][q]);
            int c = tx*6 + 2*q;
            float b0 = batt[c]     + batt[DD + c]     + batt[2*DD + c];
            float b1 = batt[c + 1] + batt[DD + c + 1] + batt[2*DD + c + 1];
            *(float2*)&out[(size_t)m*DD + c] = make_float2(v.x + b0, v.y + b1);
        }
    }
}

// ---------------- launch ---------------------------------------------------
extern "C" void kernel_launch(void* const* d_in, const int* in_sizes, int n_in,
                              void* d_out, int out_size)
{
    const float* x     = (const float*)d_in[0];
    const float* adjA  = (const float*)d_in[1];
    const float* adjB  = (const float*)d_in[2];
    const float* adjC  = (const float*)d_in[3];
    const float* mask  = (const float*)d_in[4];
    const float* mask1 = (const float*)d_in[5];
    const float* mask2 = (const float*)d_in[6];
    const float* Wenc  = (const float*)d_in[7];
    const float* benc  = (const float*)d_in[8];
    const float* Wii   = (const float*)d_in[9];
    const float* bii   = (const float*)d_in[10];
    const float* Wgru  = (const float*)d_in[11];
    const float* bgru  = (const float*)d_in[12];
    const float* Watt  = (const float*)d_in[13];
    const float* batt  = (const float*)d_in[14];
    float* out = (float*)d_out;

    encode_kernel<<<dim3(MTOT/64, 3), 256>>>(x, Wenc, benc, mask, mask1, mask2);
    for (int s = 0; s < 2; s++) {
        msg_kernel   <<<dim3(NN/128, BB, 3), 256>>>(adjA, adjB, adjC);
        gates1_kernel<<<dim3(MTOT/64, 3, 3), 256>>>(Wgru, bgru);
        gates2_kernel<<<dim3(MTOT/64, 3), 256>>>(Wgru, bgru, mask, mask1, mask2);
    }
    f1_kernel<<<dim3(MTOT/64, 3), 256>>>(Wii, bii);
    f2_kernel<<<MTOT/64, 256>>>(Watt, batt, out);
}

// round 8
// speedup vs baseline: 1.0640x; 1.0640x over previous
#include <cuda_runtime.h>
#include <math.h>

#define BB   8
#define NN   2048
#define KDIN 300
#define DD   96
#define MTOT (BB*NN)   // 16384
#define KHALF 1024

// ---------------- scratch (no runtime allocation allowed) ----------------
__device__ __align__(128) float g_h [3][MTOT][DD];
__device__ __align__(128) float g_a [3][MTOT][DD];   // msg partial, K half 0
__device__ __align__(128) float g_a2[3][MTOT][DD];   // msg partial, K half 1
__device__ __align__(128) float g_t [3][MTOT][DD];

// ---------------- f32x2 helpers ----------------
__device__ __forceinline__ unsigned long long pack2(float x, float y) {
    unsigned long long r;
    asm("mov.b64 %0, {%1,%2};" : "=l"(r) : "f"(x), "f"(y));
    return r;
}
__device__ __forceinline__ float2 unpack2(unsigned long long v) {
    float2 f;
    asm("mov.b64 {%0,%1}, %2;" : "=f"(f.x), "=f"(f.y) : "l"(v));
    return f;
}
__device__ __forceinline__ void ffma2(unsigned long long& acc, unsigned long long a, unsigned long long b) {
    asm("fma.rn.f32x2 %0, %1, %2, %0;" : "+l"(acc) : "l"(a), "l"(b));
}
__device__ __forceinline__ float sigmoidf_(float x) { return 1.f / (1.f + expf(-x)); }
__device__ __forceinline__ float lrelu(float v)     { return v > 0.f ? v : 0.2f * v; }

// =========================================================================
//  ENCODE  (unchanged from R4): h_i = mask_i * relu(x @ W_enc[i] + b_enc[i])
// =========================================================================
__device__ __forceinline__ void step32_64(const float Xs[64][32], const float Ws[32][96],
                                          int tx, int ty, unsigned long long acc[4][3])
{
    #pragma unroll
    for (int k = 0; k < 32; k++) {
        unsigned long long bp[3];
        #pragma unroll
        for (int q = 0; q < 3; q++)
            bp[q] = *(const unsigned long long*)&Ws[k][tx*6 + 2*q];
        #pragma unroll
        for (int i = 0; i < 4; i++) {
            float a = Xs[ty*4 + i][k];
            unsigned long long ap = pack2(a, a);
            #pragma unroll
            for (int q = 0; q < 3; q++) ffma2(acc[i][q], ap, bp[q]);
        }
    }
}

__global__ __launch_bounds__(256) void encode_kernel(
    const float* __restrict__ x, const float* __restrict__ Wenc, const float* __restrict__ benc,
    const float* __restrict__ mk0, const float* __restrict__ mk1, const float* __restrict__ mk2)
{
    __shared__ __align__(16) float Xs[64][32];
    __shared__ __align__(16) float Ws[32][96];
    int br = blockIdx.y;
    int m0 = blockIdx.x * 64;
    const float* mask = (br == 0) ? mk0 : ((br == 1) ? mk1 : mk2);
    const float* W = Wenc + (size_t)br * KDIN * DD;
    int tid = threadIdx.x, tx = tid & 15, ty = tid >> 4;
    unsigned long long acc[4][3] = {};
    #pragma unroll 1
    for (int k0 = 0; k0 < 320; k0 += 32) {
        #pragma unroll
        for (int l = 0; l < 8; l++) {
            int e = tid + l*256;
            int r = e >> 5, k = e & 31;
            int kk = k0 + k;
            Xs[r][k] = (kk < KDIN) ? x[(size_t)(m0 + r)*KDIN + kk] : 0.f;
        }
        #pragma unroll
        for (int l = 0; l < 12; l++) {
            int e = tid + l*256;
            int kk = e / 96, d = e % 96;
            int kg = k0 + kk;
            Ws[kk][d] = (kg < KDIN) ? W[(size_t)kg*DD + d] : 0.f;
        }
        __syncthreads();
        step32_64(Xs, Ws, tx, ty, acc);
        __syncthreads();
    }
    #pragma unroll
    for (int i = 0; i < 4; i++) {
        int m = m0 + ty*4 + i;
        float mkv = mask[m];
        #pragma unroll
        for (int q = 0; q < 3; q++) {
            float2 v = unpack2(acc[i][q]);
            int c = tx*6 + 2*q;
            float o0 = fmaxf(v.x + benc[br*DD + c],     0.f) * mkv;
            float o1 = fmaxf(v.y + benc[br*DD + c + 1], 0.f) * mkv;
            *(float2*)&g_h[br][m][c] = make_float2(o0, o1);
        }
    }
}

// =========================================================================
//  MESSAGE PASSING v2: a = adj @ h, split K in halves, 128 thr / 64-row tile
//  thread = 8 rows x 6 cols; vectorized float2 k-loads
// =========================================================================
__global__ __launch_bounds__(128, 5) void msg_kernel(
    const float* __restrict__ adjA, const float* __restrict__ adjB, const float* __restrict__ adjC)
{
    __shared__ __align__(16) float As[64][32];
    __shared__ __align__(16) float Hs[32][96];
    int br = blockIdx.z;
    int b  = blockIdx.y >> 1;
    int kz = blockIdx.y & 1;
    int n0 = blockIdx.x * 64;
    const float* adj = ((br == 0) ? adjA : ((br == 1) ? adjB : adjC)) + (size_t)b * NN * NN;
    const float* H  = &g_h[br][b * NN][0];
    float* Ao = kz ? &g_a2[br][b * NN][0] : &g_a[br][b * NN][0];
    int tid = threadIdx.x, tx = tid & 15, ty = tid >> 4;   // ty 0..7
    unsigned long long acc[8][3] = {};
    int kbeg = kz * KHALF;
    #pragma unroll 1
    for (int k0 = kbeg; k0 < kbeg + KHALF; k0 += 32) {
        #pragma unroll
        for (int l = 0; l < 4; l++) {
            int e = tid + l*128;                 // float4 index 0..511
            int r = e >> 3, k4 = e & 7;
            *(float4*)&As[r][k4*4] = *(const float4*)(adj + (size_t)(n0 + r)*NN + k0 + k4*4);
        }
        #pragma unroll
        for (int l = 0; l < 6; l++) {
            int e = tid + l*128;                 // float4 index 0..767
            int kk = e / 24, d4 = e % 24;
            *(float4*)&Hs[kk][d4*4] = *(const float4*)(H + (size_t)(k0 + kk)*DD + d4*4);
        }
        __syncthreads();
        #pragma unroll
        for (int k2 = 0; k2 < 16; k2++) {        // pairs of k
            float2 av[8];
            #pragma unroll
            for (int i = 0; i < 8; i++)
                av[i] = *(const float2*)&As[ty*8 + i][k2*2];
            #pragma unroll
            for (int kk = 0; kk < 2; kk++) {
                unsigned long long bp[3];
                #pragma unroll
                for (int q = 0; q < 3; q++)
                    bp[q] = *(const unsigned long long*)&Hs[k2*2 + kk][tx*6 + 2*q];
                #pragma unroll
                for (int i = 0; i < 8; i++) {
                    float a = kk ? av[i].y : av[i].x;
                    unsigned long long ap = pack2(a, a);
                    #pragma unroll
                    for (int q = 0; q < 3; q++) ffma2(acc[i][q], ap, bp[q]);
                }
            }
        }
        __syncthreads();
    }
    #pragma unroll
    for (int i = 0; i < 8; i++) {
        int n = n0 + ty*8 + i;
        #pragma unroll
        for (int q = 0; q < 3; q++) {
            float2 v = unpack2(acc[i][q]);
            *(float2*)&Ao[(size_t)n*DD + tx*6 + 2*q] = v;
        }
    }
}

// =========================================================================
//  FUSED GRU GATES: per 64-row tile, all of z / r / hp / rh@Wh1 / blend.
//  Dynamic SMEM: a_s[64][96] (reused for r*h), h_s[64][96], w_s[32][96]
// =========================================================================
#define GATES_SMEM ((64*96 + 64*96 + 32*96) * 4)

// acc += X(full K=96 in SMEM) @ W (global, streamed in 32-k chunks via w_s)
__device__ __forceinline__ void gemm96s(const float (*X)[96], float (*w_s)[96],
                                        const float* __restrict__ W,
                                        int tid, int tx, int ty,
                                        unsigned long long acc[4][3])
{
    #pragma unroll 1
    for (int c = 0; c < 3; c++) {
        __syncthreads();                          // previous w_s consumers done
        #pragma unroll
        for (int l = 0; l < 3; l++) {
            int e = tid + l*256;                  // float4 idx 0..767
            int kk = e / 24, d4 = e % 24;
            *(float4*)&w_s[kk][d4*4] = *(const float4*)(W + (size_t)(c*32 + kk)*DD + d4*4);
        }
        __syncthreads();
        #pragma unroll
        for (int k2 = 0; k2 < 16; k2++) {
            float2 av[4];
            #pragma unroll
            for (int i = 0; i < 4; i++)
                av[i] = *(const float2*)&X[ty*4 + i][c*32 + k2*2];
            #pragma unroll
            for (int kk = 0; kk < 2; kk++) {
                unsigned long long bp[3];
                #pragma unroll
                for (int q = 0; q < 3; q++)
                    bp[q] = *(const unsigned long long*)&w_s[k2*2 + kk][tx*6 + 2*q];
                #pragma unroll
                for (int i = 0; i < 4; i++) {
                    float a = kk ? av[i].y : av[i].x;
                    unsigned long long ap = pack2(a, a);
                    #pragma unroll
                    for (int q = 0; q < 3; q++) ffma2(acc[i][q], ap, bp[q]);
                }
            }
        }
    }
}

__global__ __launch_bounds__(256, 2) void gates_kernel(
    const float* __restrict__ Wgru, const float* __restrict__ bgru,
    const float* __restrict__ mk0, const float* __restrict__ mk1, const float* __restrict__ mk2)
{
    extern __shared__ float dsm[];
    float (*a_s)[96] = (float(*)[96])dsm;                  // also holds r*h later
    float (*h_s)[96] = (float(*)[96])(dsm + 64*96);
    float (*w_s)[96] = (float(*)[96])(dsm + 2*64*96);

    int br = blockIdx.y;
    int m0 = blockIdx.x * 64;
    const float* mask = (br == 0) ? mk0 : ((br == 1) ? mk1 : mk2);
    const float* Wb = Wgru + (size_t)(br*6) * DD * DD;     // z0,z1,r0,r1,h0,h1
    const float* bb = bgru + (size_t)(br*6) * DD;
    int tid = threadIdx.x, tx = tid & 15, ty = tid >> 4;   // ty 0..15, 4 rows each

    // load a = a0 + a1 partials, and h
    #pragma unroll
    for (int l = 0; l < 6; l++) {
        int e = tid + l*256;                               // float4 idx 0..1535
        int r = e / 24, d4 = e % 24;
        float4 u = *(const float4*)&g_a [br][m0 + r][d4*4];
        float4 v = *(const float4*)&g_a2[br][m0 + r][d4*4];
        float4 w; w.x = u.x+v.x; w.y = u.y+v.y; w.z = u.z+v.z; w.w = u.w+v.w;
        *(float4*)&a_s[r][d4*4] = w;
        *(float4*)&h_s[r][d4*4] = *(const float4*)&g_h[br][m0 + r][d4*4];
    }
    // (first gemm96s starts with __syncthreads(), which publishes a_s/h_s)

    unsigned long long acc[4][3];

    // ---- z = sigmoid(a@Wz0 + bz0 + h@Wz1 + bz1) -> regs ----
    #pragma unroll
    for (int i=0;i<4;i++) for (int q=0;q<3;q++) acc[i][q]=0ull;
    gemm96s(a_s, w_s, Wb + 0*DD*DD, tid, tx, ty, acc);
    gemm96s(h_s, w_s, Wb + 1*DD*DD, tid, tx, ty, acc);
    float2 zr[4][3];
    #pragma unroll
    for (int i = 0; i < 4; i++)
        #pragma unroll
        for (int q = 0; q < 3; q++) {
            float2 v = unpack2(acc[i][q]);
            int c = tx*6 + 2*q;
            zr[i][q].x = sigmoidf_(v.x + bb[0*DD + c]     + bb[1*DD + c]);
            zr[i][q].y = sigmoidf_(v.y + bb[0*DD + c + 1] + bb[1*DD + c + 1]);
        }

    // ---- hp = a@Wh0 -> regs ----
    #pragma unroll
    for (int i=0;i<4;i++) for (int q=0;q<3;q++) acc[i][q]=0ull;
    gemm96s(a_s, w_s, Wb + 4*DD*DD, tid, tx, ty, acc);
    float2 hp[4][3];
    #pragma unroll
    for (int i=0;i<4;i++) for (int q=0;q<3;q++) hp[i][q] = unpack2(acc[i][q]);

    // ---- r = sigmoid(a@Wr0 + br0 + h@Wr1 + br1); rh = r*h -> a_s ----
    #pragma unroll
    for (int i=0;i<4;i++) for (int q=0;q<3;q++) acc[i][q]=0ull;
    gemm96s(a_s, w_s, Wb + 2*DD*DD, tid, tx, ty, acc);
    gemm96s(h_s, w_s, Wb + 3*DD*DD, tid, tx, ty, acc);
    __syncthreads();                       // all reads of a_s complete
    #pragma unroll
    for (int i = 0; i < 4; i++)
        #pragma unroll
        for (int q = 0; q < 3; q++) {
            float2 v = unpack2(acc[i][q]);
            int c = tx*6 + 2*q;
            float2 hv = *(const float2*)&h_s[ty*4 + i][c];
            float r0 = sigmoidf_(v.x + bb[2*DD + c]     + bb[3*DD + c]);
            float r1 = sigmoidf_(v.y + bb[2*DD + c + 1] + bb[3*DD + c + 1]);
            *(float2*)&a_s[ty*4 + i][c] = make_float2(r0*hv.x, r1*hv.y);
        }
    // (next gemm96s's leading __syncthreads publishes rh)

    // ---- hh_part = rh@Wh1 ----
    #pragma unroll
    for (int i=0;i<4;i++) for (int q=0;q<3;q++) acc[i][q]=0ull;
    gemm96s(a_s, w_s, Wb + 5*DD*DD, tid, tx, ty, acc);

    // ---- blend: hh = relu(mask*(hp+bh0+rhWh1+bh1)); h = hh*z + h*(1-z) ----
    #pragma unroll
    for (int i = 0; i < 4; i++) {
        int m = m0 + ty*4 + i;
        float mkv = mask[m];
        #pragma unroll
        for (int q = 0; q < 3; q++) {
            float2 v = unpack2(acc[i][q]);
            int c = tx*6 + 2*q;
            float2 hv = *(const float2*)&h_s[ty*4 + i][c];
            float hh0 = fmaxf(mkv * (v.x + hp[i][q].x + bb[4*DD + c]     + bb[5*DD + c]),     0.f);
            float hh1 = fmaxf(mkv * (v.y + hp[i][q].y + bb[4*DD + c + 1] + bb[5*DD + c + 1]), 0.f);
            float o0 = hh0*zr[i][q].x + hv.x*(1.f - zr[i][q].x);
            float o1 = hh1*zr[i][q].y + hv.y*(1.f - zr[i][q].y);
            *(float2*)&g_h[br][m][c] = make_float2(o0, o1);
        }
    }
}

// =========================================================================
//  f1 / f2  (unchanged from R4)
// =========================================================================
__device__ __forceinline__ void mm96(const float* __restrict__ In, const float* __restrict__ W,
                                     int m0, int tid, unsigned long long acc[4][3])
{
    __shared__ __align__(16) float Xs[64][32];
    __shared__ __align__(16) float Ws[32][96];
    int tx = tid & 15, ty = tid >> 4;
    #pragma unroll 1
    for (int k0 = 0; k0 < DD; k0 += 32) {
        #pragma unroll
        for (int l = 0; l < 2; l++) {
            int e = tid + l*256;
            int r = e >> 3, k4 = e & 7;
            *(float4*)&Xs[r][k4*4] = *(const float4*)(In + (size_t)(m0 + r)*DD + k0 + k4*4);
        }
        #pragma unroll
        for (int l = 0; l < 3; l++) {
            int e = tid + l*256;
            int kk = e / 24, d4 = e % 24;
            *(float4*)&Ws[kk][d4*4] = *(const float4*)(W + (size_t)(k0 + kk)*DD + d4*4);
        }
        __syncthreads();
        step32_64(Xs, Ws, tx, ty, acc);
        __syncthreads();
    }
}

__device__ __forceinline__ void mm96pairL(const float* __restrict__ T0, const float* __restrict__ T1,
                                          const float* __restrict__ W, int m0, int tid,
                                          unsigned long long acc[4][3])
{
    __shared__ __align__(16) float Xs[64][32];
    __shared__ __align__(16) float Ws[32][96];
    int tx = tid & 15, ty = tid >> 4;
    #pragma unroll 1
    for (int k0 = 0; k0 < DD; k0 += 32) {
        #pragma unroll
        for (int l = 0; l < 2; l++) {
            int e = tid + l*256;
            int r = e >> 3, k4 = e & 7;
            size_t off = (size_t)(m0 + r)*DD + k0 + k4*4;
            float4 u = *(const float4*)(T0 + off);
            float4 v = *(const float4*)(T1 + off);
            float4 w;
            w.x = lrelu(u.x + v.x); w.y = lrelu(u.y + v.y);
            w.z = lrelu(u.z + v.z); w.w = lrelu(u.w + v.w);
            *(float4*)&Xs[r][k4*4] = w;
        }
        #pragma unroll
        for (int l = 0; l < 3; l++) {
            int e = tid + l*256;
            int kk = e / 24, d4 = e % 24;
            *(float4*)&Ws[kk][d4*4] = *(const float4*)(W + (size_t)(k0 + kk)*DD + d4*4);
        }
        __syncthreads();
        step32_64(Xs, Ws, tx, ty, acc);
        __syncthreads();
    }
}

__global__ __launch_bounds__(256) void f1_kernel(
    const float* __restrict__ Wii, const float* __restrict__ bii)
{
    int br = blockIdx.y;
    int m0 = blockIdx.x * 64;
    int tid = threadIdx.x, tx = tid & 15, ty = tid >> 4;
    unsigned long long acc[4][3] = {};
    mm96(&g_h[br][0][0], Wii + (size_t)br*DD*DD, m0, tid, acc);
    #pragma unroll
    for (int i = 0; i < 4; i++) {
        int m = m0 + ty*4 + i;
        #pragma unroll
        for (int q = 0; q < 3; q++) {
            float2 v = unpack2(acc[i][q]);
            int c = tx*6 + 2*q;
            *(float2*)&g_t[br][m][c] = make_float2(v.x + bii[br*DD + c],
                                                   v.y + bii[br*DD + c + 1]);
        }
    }
}

__global__ __launch_bounds__(256) void f2_kernel(
    const float* __restrict__ Watt, const float* __restrict__ batt, float* __restrict__ out)
{
    int m0 = blockIdx.x * 64;
    int tid = threadIdx.x, tx = tid & 15, ty = tid >> 4;
    unsigned long long acc[4][3] = {};
    #pragma unroll 1
    for (int j = 0; j < 3; j++) {
        const float* T0 = &g_t[j][0][0];
        const float* T1 = &g_t[(j + 1) % 3][0][0];
        mm96pairL(T0, T1, Watt + (size_t)j*DD*DD, m0, tid, acc);
    }
    #pragma unroll
    for (int i = 0; i < 4; i++) {
        int m = m0 + ty*4 + i;
        #pragma unroll
        for (int q = 0; q < 3; q++) {
            float2 v = unpack2(acc[i][q]);
            int c = tx*6 + 2*q;
            float b0 = batt[c]     + batt[DD + c]     + batt[2*DD + c];
            float b1 = batt[c + 1] + batt[DD + c + 1] + batt[2*DD + c + 1];
            *(float2*)&out[(size_t)m*DD + c] = make_float2(v.x + b0, v.y + b1);
        }
    }
}

// =========================================================================
//  launch
// =========================================================================
extern "C" void kernel_launch(void* const* d_in, const int* in_sizes, int n_in,
                              void* d_out, int out_size)
{
    const float* x     = (const float*)d_in[0];
    const float* adjA  = (const float*)d_in[1];
    const float* adjB  = (const float*)d_in[2];
    const float* adjC  = (const float*)d_in[3];
    const float* mask  = (const float*)d_in[4];
    const float* mask1 = (const float*)d_in[5];
    const float* mask2 = (const float*)d_in[6];
    const float* Wenc  = (const float*)d_in[7];
    const float* benc  = (const float*)d_in[8];
    const float* Wii   = (const float*)d_in[9];
    const float* bii   = (const float*)d_in[10];
    const float* Wgru  = (const float*)d_in[11];
    const float* bgru  = (const float*)d_in[12];
    const float* Watt  = (const float*)d_in[13];
    const float* batt  = (const float*)d_in[14];
    float* out = (float*)d_out;

    cudaFuncSetAttribute(gates_kernel, cudaFuncAttributeMaxDynamicSharedMemorySize, GATES_SMEM);

    encode_kernel<<<dim3(MTOT/64, 3), 256>>>(x, Wenc, benc, mask, mask1, mask2);
    for (int s = 0; s < 2; s++) {
        msg_kernel  <<<dim3(NN/64, BB*2, 3), 128>>>(adjA, adjB, adjC);
        gates_kernel<<<dim3(MTOT/64, 3), 256, GATES_SMEM>>>(Wgru, bgru, mask, mask1, mask2);
    }
    f1_kernel<<<dim3(MTOT/64, 3), 256>>>(Wii, bii);
    f2_kernel<<<MTOT/64, 256>>>(Watt, batt, out);
}